// round 15
// baseline (speedup 1.0000x reference)
#include <cuda_runtime.h>
#include <cuda_fp16.h>
#include <cstdint>

#define N_NODES  50000
#define N_EDGES  800000
#define N_GRAPHS 512
#define N_IDS    51
#define F_IN     128
#define DD       256
#define EPS      1e-5f
#define NEG_SLOPE 0.01f
#define NSB      196          // ceil(N_NODES/256) scan blocks
#define HIST_BLOCKS 3125      // ceil(N_EDGES/256)
#define PREP_BLOCKS (N_IDS + 1 + DD * DD / 2 / 256)
#define GATHER_BLOCKS 1024

typedef unsigned long long ull;

// ---------------- scratch (device globals; zero-initialized at load) --------
// INVARIANT: every mutable counter/accumulator below is zero at the start of
// each kernel_launch call and is restored to zero before the call finishes.
__device__ float g_bufA[N_NODES * DD];   // H2 (as __half)
__device__ float g_bufB[N_NODES * DD];   // agg1 (as __half) -> agg2 (fp32)
__device__ float g_HT[N_IDS * DD];       // emb_table @ W1^T + bc1
__device__ __half g_W2h[DD * DD];        // c2_lin_w as fp16
__device__ float g_C1[4 * DD];
__device__ float g_C2[4 * DD];
__device__ float g_bc2[DD];
__device__ float g_bnsum1[DD];           // self-resetting
__device__ float g_bnsq1[DD];            // self-resetting
__device__ float g_bnsum2[DD];           // self-resetting
__device__ float g_bnsq2[DD];            // self-resetting
__device__ float g_sc[DD];
__device__ float g_sh[DD];
__device__ float g_gate[N_NODES];
__device__ int   g_wq1, g_wq2;           // self-resetting
__device__ int   g_done1, g_done2;       // self-resetting
// CSR
__device__ int    g_deg[N_NODES];        // self-resetting (zeroed by attn)
__device__ int    g_start[N_NODES];
__device__ int    g_cursor[N_NODES];
__device__ int2   g_sp[N_EDGES];         // {src, srcnid}
__device__ float4 g_eas[N_EDGES];
__device__ int    g_part[NSB];
__device__ int    g_flag[NSB];           // self-resetting (zeroed by fill)

// ---------------- helpers ---------------------------------------------------
__device__ __forceinline__ float leaky(float v) {
    return v >= 0.f ? v : NEG_SLOPE * v;
}
__device__ __forceinline__ ull dup2(float x) {
    ull r; unsigned u = __float_as_uint(x);
    asm("mov.b64 %0, {%1, %1};" : "=l"(r) : "r"(u));
    return r;
}
__device__ __forceinline__ void fma2(ull& d, ull a, ull b) {
    asm("fma.rn.f32x2 %0, %1, %2, %0;" : "+l"(d) : "l"(a), "l"(b));
}
__device__ __forceinline__ float2 up2(ull v) {
    float2 f; asm("mov.b64 {%0, %1}, %2;" : "=f"(f.x), "=f"(f.y) : "l"(v));
    return f;
}
__device__ __forceinline__ ull pack2(float lo, float hi) {
    ull r;
    asm("mov.b64 %0, {%1, %2};" : "=l"(r) : "f"(lo), "f"(hi));
    return r;
}
__device__ __forceinline__ void mma_f16(float d[4], const unsigned a[4],
                                        unsigned b0, unsigned b1) {
    asm volatile(
        "mma.sync.aligned.m16n8k16.row.col.f32.f16.f16.f32 "
        "{%0,%1,%2,%3}, {%4,%5,%6,%7}, {%8,%9}, {%0,%1,%2,%3};"
        : "+f"(d[0]), "+f"(d[1]), "+f"(d[2]), "+f"(d[3])
        : "r"(a[0]), "r"(a[1]), "r"(a[2]), "r"(a[3]), "r"(b0), "r"(b1));
}

// ---------------- merged hist + prep ------------------------------------------
// blocks [0, HIST_BLOCKS)                : degree histogram
// blocks [HIST_BLOCKS, +N_IDS)           : HT rows (with inline bc1)
// block  HIST_BLOCKS + N_IDS             : C1 / C2 / bc2
// blocks (HIST_BLOCKS + N_IDS, +128]     : W2 -> fp16
__global__ void hist_prep_kernel(
    const int* __restrict__ dst,
    const float* __restrict__ emb,
    const float* __restrict__ l2w1, const float* __restrict__ l2b1,
    const float* __restrict__ lw1,  const float* __restrict__ lb1,
    const float* __restrict__ l2w2, const float* __restrict__ l2b2,
    const float* __restrict__ lw2,  const float* __restrict__ lb2)
{
    int blk = blockIdx.x;
    int d = threadIdx.x;
    if (blk < HIST_BLOCKS) {
        int e = blk * 256 + d;
        if (e < N_EDGES) atomicAdd(&g_deg[__ldg(dst + e)], 1);
        return;
    }
    int pb = blk - HIST_BLOCKS;
    if (pb < N_IDS) {
        __shared__ float ev[F_IN];
        if (d < F_IN) ev[d] = emb[pb * F_IN + d];
        __syncthreads();
        const float* wr = lw1 + (size_t)d * F_IN;
        float s = 0.f, bb = 0.f;
#pragma unroll 8
        for (int f = 0; f < F_IN; f++) {
            float w = __ldg(wr + f);
            s += ev[f] * w;
            bb += __ldg(l2b1 + f) * w;
        }
        g_HT[pb * DD + d] = s + bb + lb1[d];
    } else if (pb == N_IDS) {
        {
            float a0 = 0.f, a1 = 0.f, a2 = 0.f, a3 = 0.f;
            for (int f = 0; f < F_IN; f++) {
                float w = lw1[d * F_IN + f];
                float4 l2 = *(const float4*)(l2w1 + f * 4);
                a0 += l2.x * w; a1 += l2.y * w; a2 += l2.z * w; a3 += l2.w * w;
            }
            g_C1[0 * DD + d] = a0; g_C1[1 * DD + d] = a1;
            g_C1[2 * DD + d] = a2; g_C1[3 * DD + d] = a3;
        }
        {
            float a0 = 0.f, a1 = 0.f, a2 = 0.f, a3 = 0.f, bb = 0.f;
            for (int f = 0; f < DD; f++) {
                float w = lw2[d * DD + f];
                float4 l2 = *(const float4*)(l2w2 + f * 4);
                a0 += l2.x * w; a1 += l2.y * w; a2 += l2.z * w; a3 += l2.w * w;
                bb += l2b2[f] * w;
            }
            g_C2[0 * DD + d] = a0; g_C2[1 * DD + d] = a1;
            g_C2[2 * DD + d] = a2; g_C2[3 * DD + d] = a3;
            g_bc2[d] = bb + lb2[d];
        }
    } else {
        int i = (pb - N_IDS - 1) * 256 + d;
        float2 v = __ldg((const float2*)lw2 + i);
        *((__half2*)g_W2h + i) = __floats2half2_rn(v.x, v.y);
    }
}

// ---------------- single-pass scan (decoupled lookback, 196 co-resident) -----
__global__ void scan_kernel() {
    __shared__ int sh[256];
    __shared__ int sexcl;
    int blk = blockIdx.x;
    int t = threadIdx.x;
    int i = blk * 256 + t;
    int v = (i < N_NODES) ? g_deg[i] : 0;
    sh[t] = v;
    if (t == 0) sexcl = 0;
    __syncthreads();
#pragma unroll
    for (int off = 1; off < 256; off <<= 1) {
        int tv = (t >= off) ? sh[t - off] : 0;
        __syncthreads();
        sh[t] += tv;
        __syncthreads();
    }
    if (t == 255) {
        g_part[blk] = sh[255];
        __threadfence();
        *((volatile int*)&g_flag[blk]) = 1;
    }
    // lookback: thread t waits for block t (< blk) and adds its aggregate
    if (t < blk) {
        while (*((volatile int*)&g_flag[t]) == 0) {}
        __threadfence();
        atomicAdd(&sexcl, *((volatile int*)&g_part[t]));
    }
    __syncthreads();
    if (i < N_NODES) {
        int s = sh[t] - v + sexcl;
        g_start[i] = s;
        g_cursor[i] = s;
    }
}

// ---------------- fill (+ flag reset) -----------------------------------------
__global__ void fill_kernel(const int* __restrict__ src,
                            const int* __restrict__ dst,
                            const float* __restrict__ ea,
                            const int* __restrict__ node_ids) {
    int e = blockIdx.x * blockDim.x + threadIdx.x;
    if (e < NSB) g_flag[e] = 0;     // reset scan flags for next call
    if (e < N_EDGES) {
        int d = __ldg(dst + e);
        int s = __ldg(src + e);
        int p = atomicAdd(&g_cursor[d], 1);
        g_sp[p] = make_int2(s, __ldg(node_ids + s));
        g_eas[p] = __ldg((const float4*)ea + e);
    }
}

// ---------------- GEMM (fp16 HMMA m16n8k16, fp32 accum, half in/out) ---------
__global__ void __launch_bounds__(256)
gemm_f16(const __half* __restrict__ A,
         const float* __restrict__ sc, const float* __restrict__ sh,
         const __half* __restrict__ Wh, const float* __restrict__ bias,
         __half* __restrict__ out, int M, int K)
{
    __shared__ unsigned As[128 * 20];
    __shared__ unsigned Bs[128 * 20];
    int t = threadIdx.x;
    int lane = t & 31;
    int wid = t >> 5;
    int wm = wid & 3, wn = wid >> 2;
    int bm = blockIdx.x * 128;
    int bn = blockIdx.y * 128;

    int lrow = t >> 1;
    int lh = t & 1;

    int gid = lane >> 2;
    int c = lane & 3;

    int m0 = bm + lrow;
    int mc = m0 < M ? m0 : (M - 1);
    const __half* Arow = A + (size_t)mc * K;
    const __half* Wrow = Wh + (size_t)(bn + lrow) * K;

    float d[2][8][4];
#pragma unroll
    for (int i = 0; i < 2; i++)
#pragma unroll
        for (int j = 0; j < 8; j++)
#pragma unroll
            for (int q = 0; q < 4; q++) d[i][j][q] = 0.f;

    uint4 ra0, ra1, rb0, rb1;

    auto load_stage = [&](int kc) {
        int kb = kc + lh * 16;
        ra0 = __ldg((const uint4*)(Arow + kb));
        ra1 = __ldg((const uint4*)(Arow + kb + 8));
        rb0 = __ldg((const uint4*)(Wrow + kb));
        rb1 = __ldg((const uint4*)(Wrow + kb + 8));
#pragma unroll
        for (int q = 0; q < 8; q++) {
            unsigned* p = (q < 4) ? (&ra0.x + q) : (&ra1.x + (q - 4));
            float2 f = __half22float2(*(__half2*)p);
            int ch = kb + q * 2;
            float2 s = __ldg((const float2*)(sc + ch));
            float2 hh = __ldg((const float2*)(sh + ch));
            f.x = leaky(f.x * s.x + hh.x);
            f.y = leaky(f.y * s.y + hh.y);
            __half2 r = __floats2half2_rn(f.x, f.y);
            *p = *(unsigned*)&r;
        }
    };
    auto store_stage = [&]() {
        unsigned* ap = As + lrow * 20 + lh * 8;
        unsigned* bp = Bs + lrow * 20 + lh * 8;
        *(uint4*)(ap)     = ra0;
        *(uint4*)(ap + 4) = ra1;
        *(uint4*)(bp)     = rb0;
        *(uint4*)(bp + 4) = rb1;
    };

    load_stage(0);
    store_stage();
    __syncthreads();

    for (int kc = 0; kc < K; kc += 32) {
        bool more = (kc + 32) < K;
        if (more) load_stage(kc + 32);
#pragma unroll
        for (int ks = 0; ks < 2; ks++) {
            int kp = ks * 8 + c;
            unsigned a[2][4];
#pragma unroll
            for (int i = 0; i < 2; i++) {
                int r = (wm * 32 + i * 16 + gid) * 20;
                a[i][0] = As[r + kp];
                a[i][1] = As[r + 8 * 20 + kp];
                a[i][2] = As[r + kp + 4];
                a[i][3] = As[r + 8 * 20 + kp + 4];
            }
#pragma unroll
            for (int j = 0; j < 8; j++) {
                int rn = (wn * 64 + j * 8 + gid) * 20;
                unsigned b0 = Bs[rn + kp];
                unsigned b1 = Bs[rn + kp + 4];
                mma_f16(d[0][j], a[0], b0, b1);
                mma_f16(d[1][j], a[1], b0, b1);
            }
        }
        if (more) {
            __syncthreads();
            store_stage();
            __syncthreads();
        }
    }

    float2 bsv[8];
#pragma unroll
    for (int j = 0; j < 8; j++) {
        int col = bn + wn * 64 + j * 8 + c * 2;
        bsv[j] = __ldg((const float2*)(bias + col));
    }
#pragma unroll
    for (int i = 0; i < 2; i++) {
        int rg0 = bm + wm * 32 + i * 16 + gid;
        int rg1 = rg0 + 8;
#pragma unroll
        for (int j = 0; j < 8; j++) {
            int col = bn + wn * 64 + j * 8 + c * 2;
            if (rg0 < M)
                *(__half2*)(out + (size_t)rg0 * DD + col) =
                    __floats2half2_rn(d[i][j][0] + bsv[j].x, d[i][j][1] + bsv[j].y);
            if (rg1 < M)
                *(__half2*)(out + (size_t)rg1 * DD + col) =
                    __floats2half2_rn(d[i][j][2] + bsv[j].x, d[i][j][3] + bsv[j].y);
        }
    }
}

// ---------------- per-edge packed accumulate ---------------------------------
__device__ __forceinline__ void edge_accum(
    ull acc[4], float4 at, const ull hh[4],
    const ull c0p[4], const ull c1p[4], const ull c2p[4], const ull c3p[4])
{
    const ull ABS2 = 0x7fffffff7fffffffull;
    const ull D505 = 0x3f0147ae3f0147aeull;
    const ull D495 = 0x3efd70a43efd70a4ull;
    ull ax = dup2(at.x), ay = dup2(at.y), az = dup2(at.z), aw = dup2(at.w);
#pragma unroll
    for (int i = 0; i < 4; i++) {
        ull m = hh[i];
        fma2(m, ax, c0p[i]); fma2(m, ay, c1p[i]);
        fma2(m, az, c2p[i]); fma2(m, aw, c3p[i]);
        ull ab = m & ABS2;
        fma2(acc[i], D505, m);
        fma2(acc[i], D495, ab);
    }
}

// ---------------- CSR gather (work stealing; BN fused; self-resetting) --------
template <bool HALF_IN, bool HALF_OUT, bool USE_NID>
__global__ void gather_kernel(const void* __restrict__ Hv,
                              const float* __restrict__ C,
                              void* __restrict__ aggv,
                              float* __restrict__ bnsum,
                              float* __restrict__ bnsq,
                              int* __restrict__ wq,
                              int* __restrict__ done,
                              const float* __restrict__ bnw,
                              const float* __restrict__ bnb)
{
    __shared__ float ssum[DD];
    __shared__ float ssq[DD];
    __shared__ int slast;
    int t = threadIdx.x;
    ssum[t] = 0.f; ssq[t] = 0.f;
    __syncthreads();

    int lane = t & 31;
    int d0 = lane * 8;

    ull c0p[4], c1p[4], c2p[4], c3p[4];
    {
        ulonglong2 u;
        u = *(const ulonglong2*)(C + 0 * DD + d0);     c0p[0] = u.x; c0p[1] = u.y;
        u = *(const ulonglong2*)(C + 0 * DD + d0 + 4); c0p[2] = u.x; c0p[3] = u.y;
        u = *(const ulonglong2*)(C + 1 * DD + d0);     c1p[0] = u.x; c1p[1] = u.y;
        u = *(const ulonglong2*)(C + 1 * DD + d0 + 4); c1p[2] = u.x; c1p[3] = u.y;
        u = *(const ulonglong2*)(C + 2 * DD + d0);     c2p[0] = u.x; c2p[1] = u.y;
        u = *(const ulonglong2*)(C + 2 * DD + d0 + 4); c2p[2] = u.x; c2p[3] = u.y;
        u = *(const ulonglong2*)(C + 3 * DD + d0);     c3p[0] = u.x; c3p[1] = u.y;
        u = *(const ulonglong2*)(C + 3 * DD + d0 + 4); c3p[2] = u.x; c3p[3] = u.y;
    }

    const float* Hf = (const float*)Hv;
    const __half* Hh = (const __half*)Hv;

    auto load_h = [&](int row, ull hh[4]) {
        if (HALF_IN) {
            uint4 u = __ldg((const uint4*)(Hh + (size_t)row * DD + d0));
            float2 f0 = __half22float2(*(__half2*)&u.x);
            float2 f1 = __half22float2(*(__half2*)&u.y);
            float2 f2 = __half22float2(*(__half2*)&u.z);
            float2 f3 = __half22float2(*(__half2*)&u.w);
            hh[0] = pack2(f0.x, f0.y); hh[1] = pack2(f1.x, f1.y);
            hh[2] = pack2(f2.x, f2.y); hh[3] = pack2(f3.x, f3.y);
        } else {
            const ulonglong2* hp = (const ulonglong2*)(Hf + (size_t)row * DD + d0);
            ulonglong2 p = hp[0], q = hp[1];
            hh[0] = p.x; hh[1] = p.y; hh[2] = q.x; hh[3] = q.y;
        }
    };

    float sA[8], qA[8];
#pragma unroll
    for (int i = 0; i < 8; i++) { sA[i] = 0.f; qA[i] = 0.f; }

    int n = 0;
    if (lane == 0) n = atomicAdd(wq, 1);
    n = __shfl_sync(0xffffffffu, n, 0);
    while (n < N_NODES) {
        int nn = 0;
        if (lane == 0) nn = atomicAdd(wq, 1);
        nn = __shfl_sync(0xffffffffu, nn, 0);

        int s0 = __ldg(g_start + n);
        int dg = __ldg(g_deg + n);
        ull acc[4] = {0ull, 0ull, 0ull, 0ull};

        int j = 0;
        for (; j + 3 < dg; j += 4) {
            int2 p0 = __ldg(g_sp + s0 + j);
            int2 p1 = __ldg(g_sp + s0 + j + 1);
            int2 p2 = __ldg(g_sp + s0 + j + 2);
            int2 p3 = __ldg(g_sp + s0 + j + 3);
            int sa = USE_NID ? p0.y : p0.x;
            int sb = USE_NID ? p1.y : p1.x;
            int sc2 = USE_NID ? p2.y : p2.x;
            int sd = USE_NID ? p3.y : p3.x;
            ull ha[4], hb[4], hc[4], hd[4];
            load_h(sa, ha); load_h(sb, hb); load_h(sc2, hc); load_h(sd, hd);
            float4 at0 = __ldg((const float4*)g_eas + s0 + j);
            float4 at1 = __ldg((const float4*)g_eas + s0 + j + 1);
            float4 at2 = __ldg((const float4*)g_eas + s0 + j + 2);
            float4 at3 = __ldg((const float4*)g_eas + s0 + j + 3);
            edge_accum(acc, at0, ha, c0p, c1p, c2p, c3p);
            edge_accum(acc, at1, hb, c0p, c1p, c2p, c3p);
            edge_accum(acc, at2, hc, c0p, c1p, c2p, c3p);
            edge_accum(acc, at3, hd, c0p, c1p, c2p, c3p);
        }
        for (; j < dg; j++) {
            int2 p0 = __ldg(g_sp + s0 + j);
            int sa = USE_NID ? p0.y : p0.x;
            float4 at0 = __ldg((const float4*)g_eas + s0 + j);
            ull ha[4];
            load_h(sa, ha);
            edge_accum(acc, at0, ha, c0p, c1p, c2p, c3p);
        }

        float2 f0 = up2(acc[0]), f1 = up2(acc[1]);
        float2 f2 = up2(acc[2]), f3 = up2(acc[3]);
        if (HALF_OUT) {
            __half2 h0 = __floats2half2_rn(f0.x, f0.y);
            __half2 h1 = __floats2half2_rn(f1.x, f1.y);
            __half2 h2 = __floats2half2_rn(f2.x, f2.y);
            __half2 h3 = __floats2half2_rn(f3.x, f3.y);
            uint4 u;
            u.x = *(unsigned*)&h0; u.y = *(unsigned*)&h1;
            u.z = *(unsigned*)&h2; u.w = *(unsigned*)&h3;
            *(uint4*)((__half*)aggv + (size_t)n * DD + d0) = u;
        } else {
            ulonglong2* op = (ulonglong2*)((float*)aggv + (size_t)n * DD + d0);
            op[0] = make_ulonglong2(acc[0], acc[1]);
            op[1] = make_ulonglong2(acc[2], acc[3]);
        }

        sA[0] += f0.x; qA[0] += f0.x * f0.x;  sA[1] += f0.y; qA[1] += f0.y * f0.y;
        sA[2] += f1.x; qA[2] += f1.x * f1.x;  sA[3] += f1.y; qA[3] += f1.y * f1.y;
        sA[4] += f2.x; qA[4] += f2.x * f2.x;  sA[5] += f2.y; qA[5] += f2.y * f2.y;
        sA[6] += f3.x; qA[6] += f3.x * f3.x;  sA[7] += f3.y; qA[7] += f3.y * f3.y;

        n = nn;
    }
#pragma unroll
    for (int i = 0; i < 8; i++) {
        atomicAdd(&ssum[d0 + i], sA[i]);
        atomicAdd(&ssq[d0 + i], qA[i]);
    }
    __syncthreads();
    atomicAdd(&bnsum[t], ssum[t]);
    atomicAdd(&bnsq[t], ssq[t]);

    // last block: compute BN scale/shift, then reset accumulators + counters
    __threadfence();
    if (t == 0) slast = (atomicAdd(done, 1) == (int)gridDim.x - 1) ? 1 : 0;
    __syncthreads();
    if (slast) {
        __threadfence();
        const float invN = 1.f / (float)N_NODES;
        float m = bnsum[t] * invN;
        float var = bnsq[t] * invN - m * m;
        float s = __ldg(bnw + t) * rsqrtf(var + EPS);
        g_sc[t] = s;
        g_sh[t] = __ldg(bnb + t) - m * s;
        bnsum[t] = 0.f;                 // self-reset for next call
        bnsq[t] = 0.f;
        if (t == 0) { *wq = 0; *done = 0; }
    }
}

// ---------------- fused attention (+ deg reset) --------------------------------
__device__ __forceinline__ int lbound(const int* a, int v) {
    int lo = 0, hi = N_NODES;
    while (lo < hi) {
        int m = (lo + hi) >> 1;
        if (__ldg(a + m) < v) lo = m + 1; else hi = m;
    }
    return lo;
}

__global__ void attn_kernel(const float* __restrict__ X,
                            const int* __restrict__ batch,
                            const float* __restrict__ gw,
                            const float* __restrict__ gb,
                            float* __restrict__ out)
{
    __shared__ int sr0, sr1;
    __shared__ float smax[8];
    __shared__ float sgmax;
    __shared__ float sE[256];
    int g = blockIdx.x;
    int t = threadIdx.x;
    int lane = t & 31, w = t >> 5;

    // deg reset for next call (512*256 = 131072 >= N_NODES)
    int gi = g * 256 + t;
    if (gi < N_NODES) g_deg[gi] = 0;

    if (t == 0) { sr0 = lbound(batch, g); sr1 = lbound(batch, g + 1); }
    __syncthreads();
    int r0 = sr0, r1 = sr1;

    float wmax = -3.4e38f;
    {
        int d0 = lane * 8;
        float gwv[8], scv[8], shv[8];
#pragma unroll
        for (int i = 0; i < 8; i++) {
            gwv[i] = __ldg(gw + d0 + i);
            scv[i] = g_sc[d0 + i];
            shv[i] = g_sh[d0 + i];
        }
        for (int n = r0 + w; n < r1; n += 8) {
            const float4* xp = (const float4*)(X + (size_t)n * DD + d0);
            float4 h0 = __ldg(xp), h1 = __ldg(xp + 1);
            float v[8] = {h0.x, h0.y, h0.z, h0.w, h1.x, h1.y, h1.z, h1.w};
            float gsum = 0.f;
#pragma unroll
            for (int i = 0; i < 8; i++)
                gsum += leaky(v[i] * scv[i] + shv[i]) * gwv[i];
#pragma unroll
            for (int off = 16; off; off >>= 1)
                gsum += __shfl_xor_sync(0xffffffffu, gsum, off);
            if (lane == 0) {
                gsum += __ldg(gb);
                g_gate[n] = gsum;
                wmax = fmaxf(wmax, gsum);
            }
        }
    }
    if (lane == 0) smax[w] = wmax;
    __syncthreads();
    if (t == 0) {
        float m = smax[0];
#pragma unroll
        for (int i = 1; i < 8; i++) m = fmaxf(m, smax[i]);
        sgmax = m;
    }
    __syncthreads();
    float gmax = sgmax;

    float sc_c = g_sc[t], sh_c = g_sh[t];
    float acc = 0.f, denom = 0.f;
    for (int c0 = r0; c0 < r1; c0 += 256) {
        int cnt = min(256, r1 - c0);
        __syncthreads();
        if (t < cnt) sE[t] = __expf(g_gate[c0 + t] - gmax);
        __syncthreads();
        for (int i = 0; i < cnt; i++) {
            float e = sE[i];
            denom += e;
            float x = __ldg(X + (size_t)(c0 + i) * DD + t);
            acc += e * leaky(x * sc_c + sh_c);
        }
    }
    out[(size_t)g * DD + t] = denom > 0.f ? acc / denom : 0.f;
}

// ---------------- launch -----------------------------------------------------
extern "C" void kernel_launch(void* const* d_in, const int* in_sizes, int n_in,
                              void* d_out, int out_size)
{
    const int*   node_ids  = (const int*)d_in[0];
    const int*   edge_index= (const int*)d_in[1];
    const float* edge_attr = (const float*)d_in[2];
    const int*   batch     = (const int*)d_in[3];
    const float* emb       = (const float*)d_in[4];
    const float* c1_lin2_w = (const float*)d_in[5];
    const float* c1_lin2_b = (const float*)d_in[6];
    const float* c1_lin_w  = (const float*)d_in[7];
    const float* c1_lin_b  = (const float*)d_in[8];
    const float* bn1_w     = (const float*)d_in[9];
    const float* bn1_b     = (const float*)d_in[10];
    const float* c2_lin2_w = (const float*)d_in[11];
    const float* c2_lin2_b = (const float*)d_in[12];
    const float* c2_lin_w  = (const float*)d_in[13];
    const float* c2_lin_b  = (const float*)d_in[14];
    const float* bn2_w     = (const float*)d_in[15];
    const float* bn2_b     = (const float*)d_in[16];
    const float* gate_w    = (const float*)d_in[17];
    const float* gate_b    = (const float*)d_in[18];
    float* out = (float*)d_out;

    const int* src = edge_index;
    const int* dst = edge_index + N_EDGES;

    float *pA, *pB, *pHT, *pC1, *pC2, *pbc2, *psc, *psh;
    float *pbs1, *pbq1, *pbs2, *pbq2;
    int *pWq1, *pWq2, *pDone1, *pDone2;
    __half* pW2h;
    cudaGetSymbolAddress((void**)&pA,    g_bufA);
    cudaGetSymbolAddress((void**)&pB,    g_bufB);
    cudaGetSymbolAddress((void**)&pHT,   g_HT);
    cudaGetSymbolAddress((void**)&pW2h,  g_W2h);
    cudaGetSymbolAddress((void**)&pC1,   g_C1);
    cudaGetSymbolAddress((void**)&pC2,   g_C2);
    cudaGetSymbolAddress((void**)&pbc2,  g_bc2);
    cudaGetSymbolAddress((void**)&psc,   g_sc);
    cudaGetSymbolAddress((void**)&psh,   g_sh);
    cudaGetSymbolAddress((void**)&pbs1,  g_bnsum1);
    cudaGetSymbolAddress((void**)&pbq1,  g_bnsq1);
    cudaGetSymbolAddress((void**)&pbs2,  g_bnsum2);
    cudaGetSymbolAddress((void**)&pbq2,  g_bnsq2);
    cudaGetSymbolAddress((void**)&pWq1,  g_wq1);
    cudaGetSymbolAddress((void**)&pWq2,  g_wq2);
    cudaGetSymbolAddress((void**)&pDone1, g_done1);
    cudaGetSymbolAddress((void**)&pDone2, g_done2);

    __half* pAh = (__half*)pA;
    __half* pBh = (__half*)pB;

    // ---- 1. hist + prep (merged) ----
    hist_prep_kernel<<<HIST_BLOCKS + PREP_BLOCKS, 256>>>(
        dst, emb, c1_lin2_w, c1_lin2_b, c1_lin_w, c1_lin_b,
        c2_lin2_w, c2_lin2_b, c2_lin_w, c2_lin_b);

    // ---- 2. single-pass lookback scan ----
    scan_kernel<<<NSB, 256>>>();

    // ---- 3. fill (+ flag reset) ----
    fill_kernel<<<(N_EDGES + 255) / 256, 256>>>(src, dst, edge_attr, node_ids);

    // ---- 4. conv1 gather (HT -> fp16 agg1) + fused BN1 + self-reset ----
    gather_kernel<false, true, true><<<GATHER_BLOCKS, 256>>>(
        pHT, pC1, pBh, pbs1, pbq1, pWq1, pDone1, bn1_w, bn1_b);

    // ---- 5. layer 2 GEMM (fp16 HMMA) ----
    dim3 gg((N_NODES + 127) / 128, DD / 128);
    gemm_f16<<<gg, 256>>>(pBh, psc, psh, pW2h, pbc2, pAh, N_NODES, DD);

    // ---- 6. conv2 gather (fp16 H2 -> fp32 agg2) + fused BN2 + self-reset ----
    gather_kernel<true, false, false><<<GATHER_BLOCKS, 256>>>(
        pAh, pC2, pB, pbs2, pbq2, pWq2, pDone2, bn2_w, bn2_b);

    // ---- 7. fused attention (+ deg reset for next call) ----
    attn_kernel<<<N_GRAPHS, 256>>>(pB, batch, gate_w, gate_b, out);
}